// round 3
// baseline (speedup 1.0000x reference)
#include <cuda_runtime.h>
#include <math.h>

// FlowMatching: per-batch Gaussian blur (separable, K=9, sigma=0.1+0.9*t[b],
// dynamic radius mask r=ceil(4*sigma), zero padding) + lerp t*blur + (1-t)*x.
// x1: [128, 3, 512, 512] fp32, t: [128] fp32, out: same as x1.
//
// Strategy: fused single-pass, smem-tiled separable convolution.
//   Tile: 128 wide x 32 tall output, halo 4 each side.
//   Phase 1: load (40 x 136) input tile (float4 interior + scalar halo cols).
//   Phase 2: horizontal 9-tap into (40 x 128) smem buffer.
//   Phase 3: vertical 9-tap + lerp, float4 stores.

#define H 512
#define W 512
#define TW 128
#define TH 32
#define RAD 4
#define KS 9
#define IN_W (TW + 2 * RAD)   // 136
#define IN_H (TH + 2 * RAD)   // 40

__global__ __launch_bounds__(256, 4)
void flowmatch_blur_kernel(const float* __restrict__ x1,
                           const float* __restrict__ t,
                           float* __restrict__ out)
{
    __shared__ float s_in[IN_H][IN_W];    // 40*136*4 = 21760 B
    __shared__ float s_h[IN_H][TW];       // 40*128*4 = 20480 B
    __shared__ float s_w[KS];

    const int tid   = threadIdx.x;
    const int plane = blockIdx.z;             // b*3 + c, 384 planes
    const int b     = plane / 3;
    const int x0    = blockIdx.x * TW;
    const int y0    = blockIdx.y * TH;

    const float tv = t[b];

    // ---- per-block 1D normalized gaussian weights (thread 0) ----
    if (tid == 0) {
        // match jnp: sigma = MIN + t*(MAX-MIN), r = ceil(4*sigma), mask |c|<=r
        float sigma = __fadd_rn(0.1f, __fmul_rn(tv, 0.9f));
        float r     = ceilf(__fmul_rn(4.0f, sigma));
        float inv2s2 = 1.0f / (2.0f * sigma * sigma);
        float sum = 0.0f;
        float wloc[KS];
        #pragma unroll
        for (int i = 0; i < KS; i++) {
            float c = (float)(i - RAD);
            float v = (fabsf(c) <= r) ? expf(-c * c * inv2s2) : 0.0f;
            wloc[i] = v;
            sum += v;
        }
        float inv = 1.0f / sum;
        #pragma unroll
        for (int i = 0; i < KS; i++) s_w[i] = wloc[i] * inv;
    }

    const float* plane_in  = x1  + (size_t)plane * (H * W);
    float*       plane_out = out + (size_t)plane * (H * W);

    // ---- Phase 1a: interior columns via float4 (always in-range in x) ----
    // 40 rows x 32 quads = 1280 float4
    for (int idx = tid; idx < IN_H * (TW / 4); idx += 256) {
        int row = idx >> 5;           // 0..39
        int q   = idx & 31;           // 0..31
        int gy  = y0 - RAD + row;
        float4 v = make_float4(0.f, 0.f, 0.f, 0.f);
        if (gy >= 0 && gy < H)
            v = *reinterpret_cast<const float4*>(plane_in + gy * W + x0 + q * 4);
        *reinterpret_cast<float4*>(&s_in[row][RAD + q * 4]) = v;
    }

    // ---- Phase 1b: halo columns (4 left, 4 right), scalar ----
    for (int idx = tid; idx < IN_H * (2 * RAD); idx += 256) {
        int row = idx >> 3;           // 0..39
        int j   = idx & 7;            // 0..7
        int gy  = y0 - RAD + row;
        int gx  = (j < RAD) ? (x0 - RAD + j) : (x0 + TW - RAD + j); // left / right
        int lx  = (j < RAD) ? j : (TW + j);                          // 0..3 / 132..135
        float v = 0.0f;
        if (gy >= 0 && gy < H && gx >= 0 && gx < W)
            v = plane_in[gy * W + gx];
        s_in[row][lx] = v;
    }

    __syncthreads();

    // ---- Phase 2: horizontal 9-tap, all 40 rows ----
    // 40 * 128 = 5120 outputs, 20 per thread
    float w0 = s_w[0], w1 = s_w[1], w2 = s_w[2], w3 = s_w[3], w4 = s_w[4],
          w5 = s_w[5], w6 = s_w[6], w7 = s_w[7], w8 = s_w[8];

    for (int idx = tid; idx < IN_H * TW; idx += 256) {
        int row = idx >> 7;           // 0..39
        int x   = idx & 127;          // 0..127
        const float* p = &s_in[row][x];
        float acc = w0 * p[0];
        acc += w1 * p[1];
        acc += w2 * p[2];
        acc += w3 * p[3];
        acc += w4 * p[4];
        acc += w5 * p[5];
        acc += w6 * p[6];
        acc += w7 * p[7];
        acc += w8 * p[8];
        s_h[row][x] = acc;
    }

    __syncthreads();

    // ---- Phase 3: vertical 9-tap + lerp, float4 stores ----
    const float omt = 1.0f - tv;
    #pragma unroll
    for (int i = 0; i < 4; i++) {
        int y  = (tid >> 5) + 8 * i;      // 0..31
        int xq = (tid & 31) * 4;          // 0,4,...,124

        float4 acc = make_float4(0.f, 0.f, 0.f, 0.f);
        #pragma unroll
        for (int d = 0; d < KS; d++) {
            float wd  = s_w[d];
            float4 hv = *reinterpret_cast<const float4*>(&s_h[y + d][xq]);
            acc.x += wd * hv.x;
            acc.y += wd * hv.y;
            acc.z += wd * hv.z;
            acc.w += wd * hv.w;
        }

        float4 orig = *reinterpret_cast<const float4*>(&s_in[y + RAD][xq + RAD]);
        float4 o;
        o.x = tv * acc.x + omt * orig.x;
        o.y = tv * acc.y + omt * orig.y;
        o.z = tv * acc.z + omt * orig.z;
        o.w = tv * acc.w + omt * orig.w;

        *reinterpret_cast<float4*>(plane_out + (size_t)(y0 + y) * W + x0 + xq) = o;
    }
}

extern "C" void kernel_launch(void* const* d_in, const int* in_sizes, int n_in,
                              void* d_out, int out_size)
{
    const float* x1 = (const float*)d_in[0];
    const float* t  = (const float*)d_in[1];
    float* out      = (float*)d_out;

    // 128 batches * 3 channels = 384 planes; 512/128=4 x-tiles, 512/32=16 y-tiles
    dim3 grid(W / TW, H / TH, 384);
    dim3 block(256);
    flowmatch_blur_kernel<<<grid, block>>>(x1, t, out);
}

// round 5
// speedup vs baseline: 1.6417x; 1.6417x over previous
#include <cuda_runtime.h>
#include <math.h>

// FlowMatching: per-batch Gaussian blur (separable, K=9, sigma=0.1+0.9*t[b],
// dynamic radius mask r=ceil(4*sigma), zero padding) + lerp t*blur + (1-t)*x.
// x1: [128, 3, 512, 512] fp32, t: [128] fp32, out: same as x1.
//
// R4: fix R3's off-by-one in the vertical rolling window (12 rows, not 13;
// was reading s_h[40][] and s_w[9] out of bounds -> illegal address).
// Optimization theory unchanged: vectorized LDS.128 in both smem phases.

#define H 512
#define W 512
#define TW 128
#define TH 32
#define RAD 4
#define KS 9
#define IN_W (TW + 2 * RAD)   // 136 floats = 544 B row stride (16B aligned)
#define IN_H (TH + 2 * RAD)   // 40

__global__ __launch_bounds__(256, 4)
void flowmatch_blur_kernel(const float* __restrict__ x1,
                           const float* __restrict__ t,
                           float* __restrict__ out)
{
    __shared__ float s_in[IN_H][IN_W];    // 21760 B
    __shared__ float s_h[IN_H][TW];       // 20480 B
    __shared__ float s_w[KS];

    const int tid   = threadIdx.x;
    const int plane = blockIdx.z;             // b*3 + c, 384 planes
    const int b     = plane / 3;
    const int x0    = blockIdx.x * TW;
    const int y0    = blockIdx.y * TH;

    const float tv = t[b];

    // ---- per-block 1D normalized gaussian weights (thread 0) ----
    if (tid == 0) {
        float sigma = __fadd_rn(0.1f, __fmul_rn(tv, 0.9f));
        float r     = ceilf(__fmul_rn(4.0f, sigma));
        float inv2s2 = 1.0f / (2.0f * sigma * sigma);
        float sum = 0.0f;
        float wloc[KS];
        #pragma unroll
        for (int i = 0; i < KS; i++) {
            float c = (float)(i - RAD);
            float v = (fabsf(c) <= r) ? expf(-c * c * inv2s2) : 0.0f;
            wloc[i] = v;
            sum += v;
        }
        float inv = 1.0f / sum;
        #pragma unroll
        for (int i = 0; i < KS; i++) s_w[i] = wloc[i] * inv;
    }

    const float* plane_in  = x1  + (size_t)plane * (H * W);
    float*       plane_out = out + (size_t)plane * (H * W);

    // ---- Phase 1a: interior columns via float4 ----
    #pragma unroll
    for (int it = 0; it < 5; it++) {
        int idx = tid + it * 256;       // 0..1279
        int row = idx >> 5;             // 0..39
        int q   = idx & 31;             // 0..31
        int gy  = y0 - RAD + row;
        float4 v = make_float4(0.f, 0.f, 0.f, 0.f);
        if (gy >= 0 && gy < H)
            v = *reinterpret_cast<const float4*>(plane_in + gy * W + x0 + q * 4);
        *reinterpret_cast<float4*>(&s_in[row][RAD + q * 4]) = v;
    }

    // ---- Phase 1b: halo columns (4 left, 4 right), scalar ----
    for (int idx = tid; idx < IN_H * (2 * RAD); idx += 256) {
        int row = idx >> 3;
        int j   = idx & 7;
        int gy  = y0 - RAD + row;
        int gx  = (j < RAD) ? (x0 - RAD + j) : (x0 + TW - RAD + j);
        int lx  = (j < RAD) ? j : (TW + j);
        float v = 0.0f;
        if (gy >= 0 && gy < H && gx >= 0 && gx < W)
            v = plane_in[gy * W + gx];
        s_in[row][lx] = v;
    }

    __syncthreads();

    const float w0 = s_w[0], w1 = s_w[1], w2 = s_w[2], w3 = s_w[3], w4 = s_w[4],
                w5 = s_w[5], w6 = s_w[6], w7 = s_w[7], w8 = s_w[8];

    // ---- Phase 2: horizontal 9-tap, vectorized: 3 LDS.128 -> 4 outputs ----
    // 40 rows x 32 quads = 1280 quads, 5 per thread
    #pragma unroll
    for (int it = 0; it < 5; it++) {
        int idx = tid + it * 256;       // 0..1279
        int row = idx >> 5;             // 0..39
        int xq  = (idx & 31) * 4;       // 0..124 (output x of quad start)

        // inputs needed: s_in[row][xq .. xq+11]  (output x uses s_in[x..x+8])
        float4 A  = *reinterpret_cast<const float4*>(&s_in[row][xq]);
        float4 Bv = *reinterpret_cast<const float4*>(&s_in[row][xq + 4]);
        float4 Cv = *reinterpret_cast<const float4*>(&s_in[row][xq + 8]);
        float f0 = A.x,  f1 = A.y,  f2 = A.z,  f3 = A.w;
        float f4 = Bv.x, f5 = Bv.y, f6 = Bv.z, f7 = Bv.w;
        float f8 = Cv.x, f9 = Cv.y, f10 = Cv.z, f11 = Cv.w;

        float4 o;
        o.x = w0*f0 + w1*f1 + w2*f2 + w3*f3 + w4*f4 + w5*f5 + w6*f6 + w7*f7 + w8*f8;
        o.y = w0*f1 + w1*f2 + w2*f3 + w3*f4 + w4*f5 + w5*f6 + w6*f7 + w7*f8 + w8*f9;
        o.z = w0*f2 + w1*f3 + w2*f4 + w3*f5 + w4*f6 + w5*f7 + w6*f8 + w7*f9 + w8*f10;
        o.w = w0*f3 + w1*f4 + w2*f5 + w3*f6 + w4*f7 + w5*f8 + w6*f9 + w7*f10 + w8*f11;

        *reinterpret_cast<float4*>(&s_h[row][xq]) = o;
    }

    __syncthreads();

    // ---- Phase 3: vertical 9-tap + lerp, rolling 12-row window, 4 stacked quads ----
    // thread -> xq = (tid&31)*4, ybase = (tid>>5)*4  (8 y-groups x 32 x-quads = 256)
    {
        const int xq    = (tid & 31) * 4;
        const int ybase = (tid >> 5) * 4;   // 0,4,...,28
        const float omt = 1.0f - tv;

        float4 acc0 = make_float4(0.f,0.f,0.f,0.f);
        float4 acc1 = make_float4(0.f,0.f,0.f,0.f);
        float4 acc2 = make_float4(0.f,0.f,0.f,0.f);
        float4 acc3 = make_float4(0.f,0.f,0.f,0.f);

        // rows ybase .. ybase+11 of s_h feed outputs ybase..ybase+3
        // (output y uses s_h[y .. y+8]; union for 4 outputs = 12 rows)
        #pragma unroll
        for (int r = 0; r < 12; r++) {
            float4 hv = *reinterpret_cast<const float4*>(&s_h[ybase + r][xq]);
            if (r <= 8) {
                float wd = s_w[r];
                acc0.x += wd * hv.x; acc0.y += wd * hv.y;
                acc0.z += wd * hv.z; acc0.w += wd * hv.w;
            }
            if (r >= 1 && r <= 9) {
                float wd = s_w[r - 1];
                acc1.x += wd * hv.x; acc1.y += wd * hv.y;
                acc1.z += wd * hv.z; acc1.w += wd * hv.w;
            }
            if (r >= 2 && r <= 10) {
                float wd = s_w[r - 2];
                acc2.x += wd * hv.x; acc2.y += wd * hv.y;
                acc2.z += wd * hv.z; acc2.w += wd * hv.w;
            }
            if (r >= 3) {                    // r max 11 -> weight index max 8
                float wd = s_w[r - 3];
                acc3.x += wd * hv.x; acc3.y += wd * hv.y;
                acc3.z += wd * hv.z; acc3.w += wd * hv.w;
            }
        }

        #pragma unroll
        for (int j = 0; j < 4; j++) {
            float4 acc = (j == 0) ? acc0 : (j == 1) ? acc1 : (j == 2) ? acc2 : acc3;
            int y = ybase + j;
            float4 orig = *reinterpret_cast<const float4*>(&s_in[y + RAD][xq + RAD]);
            float4 o;
            o.x = tv * acc.x + omt * orig.x;
            o.y = tv * acc.y + omt * orig.y;
            o.z = tv * acc.z + omt * orig.z;
            o.w = tv * acc.w + omt * orig.w;
            *reinterpret_cast<float4*>(plane_out + (size_t)(y0 + y) * W + x0 + xq) = o;
        }
    }
}

extern "C" void kernel_launch(void* const* d_in, const int* in_sizes, int n_in,
                              void* d_out, int out_size)
{
    const float* x1 = (const float*)d_in[0];
    const float* t  = (const float*)d_in[1];
    float* out      = (float*)d_out;

    dim3 grid(W / TW, H / TH, 384);   // 4 x 16 x 384 = 24576 blocks
    dim3 block(256);
    flowmatch_blur_kernel<<<grid, block>>>(x1, t, out);
}